// round 11
// baseline (speedup 1.0000x reference)
#include <cuda_runtime.h>
#include <cuda_pipeline.h>

// Sobel_16724602651101 — R10
// x: (16, 3, 512, 512) fp32 -> out: [magnitude | angle] each (16,512,512) fp32.
//
// cp.async (LDGSTS) staging: loads bypass the register file into smem
// (outstanding-load capacity = smem, not RF), freeing registers for an
// occupancy-rich compute phase. 128x16 tile/block, 4x2 px/thread,
// conflict-free LDS. Numeric trees frozen from the R1-R9 lineage
// (R1 grouping, exact power-of-two deferred scaling, sqrt.approx +
// __fdividef; rel_err 1.0849e-7).

#define BATCH 16
#define CH 3
#define HH 512
#define WW 512
#define HW (HH * WW)

#define TILE_W 128
#define TILE_H 16
#define LH 18            // halo rows
#define LPITCH 136       // halo cols/pitch: global cols bx0-4 .. bx0+131

#define EPS64 (64.0f * 1e-9f)
#define TINY8 (8.0f * 1e-9f)

__device__ __forceinline__ float fsqrt_approx(float a)
{
    float r;
    asm("sqrt.approx.f32 %0, %1;" : "=f"(r) : "f"(a));
    return r;
}

__global__ __launch_bounds__(256, 4)
void sobel_kernel(const float* __restrict__ x, float* __restrict__ out)
{
    __shared__ float s[CH][LH][LPITCH];

    const int bx0 = blockIdx.x * TILE_W;
    const int by0 = blockIdx.y * TILE_H;
    const int b   = blockIdx.z;
    const int tid = threadIdx.x;

    const float* __restrict__ xb = x + (size_t)b * CH * HW;

    // ---- async load of the 3-channel halo tile into smem (RF-free) ----
    const bool interior = (bx0 >= 4) && (bx0 + 132 <= WW);

    if (interior) {
        // 3 * 18 * 34 float4 copies = 1836, ~7/thread
        #pragma unroll 1
        for (int i = tid; i < CH * LH * (LPITCH / 4); i += 256) {
            int c   = i / (LH * (LPITCH / 4));
            int rem = i - c * (LH * (LPITCH / 4));
            int r   = rem / (LPITCH / 4);
            int q   = rem - r * (LPITCH / 4);
            int gr  = min(max(by0 - 1 + r, 0), HH - 1);
            __pipeline_memcpy_async(&s[c][r][4 * q],
                                    xb + (size_t)c * HW + (size_t)gr * WW + (bx0 - 4) + 4 * q,
                                    16);
        }
    } else {
        // x-edge blocks: scalar cp.async with clamped columns
        #pragma unroll 1
        for (int i = tid; i < CH * LH * LPITCH; i += 256) {
            int c   = i / (LH * LPITCH);
            int rem = i - c * (LH * LPITCH);
            int r   = rem / LPITCH;
            int j   = rem - r * LPITCH;
            int gr  = min(max(by0 - 1 + r, 0), HH - 1);
            int gc  = min(max(bx0 - 4 + j, 0), WW - 1);
            __pipeline_memcpy_async(&s[c][r][j],
                                    xb + (size_t)c * HW + (size_t)gr * WW + gc,
                                    4);
        }
    }
    __pipeline_commit();
    __pipeline_wait_prior(0);
    __syncthreads();

    // ---- compute: 4 cols x 2 rows per thread ----
    const int lane = tid & 31;           // col group: px cols bx0 + 4*lane ..+3
    const int wy   = tid >> 5;           // row pair: out rows by0+2wy, +2wy+1
    const int lc   = 4 * lane;           // local col of first px minus offset:
                                         // window local cols lc+3 .. lc+8

    float bm[2][4], bgx[2][4], bgy[2][4];

    #pragma unroll
    for (int c = 0; c < CH; c++) {
        // 4 input rows (local 2wy .. 2wy+3) x 6 cols
        float w[4][6];
        #pragma unroll
        for (int i = 0; i < 4; i++) {
            const float* __restrict__ row = &s[c][2 * wy + i][0];
            float4 v = *(const float4*)(row + lc + 4);
            w[i][0] = row[lc + 3];
            w[i][1] = v.x; w[i][2] = v.y; w[i][3] = v.z; w[i][4] = v.w;
            w[i][5] = row[lc + 8];
        }

        // horizontal diffs per input row (rows 1,2 shared by both out rows)
        float dr[4][4];
        #pragma unroll
        for (int i = 0; i < 4; i++)
            #pragma unroll
            for (int p = 0; p < 4; p++) dr[i][p] = w[i][p + 2] - w[i][p];

        // vertical diffs per output row
        float vd[2][6];
        #pragma unroll
        for (int j = 0; j < 6; j++) { vd[0][j] = w[2][j] - w[0][j];
                                      vd[1][j] = w[3][j] - w[1][j]; }

        #pragma unroll
        for (int rr = 0; rr < 2; rr++) {
            #pragma unroll
            for (int p = 0; p < 4; p++) {
                // 8x-scaled gx/gy, R1's exact grouping
                float gx = dr[rr][p] + 2.0f * dr[rr + 1][p] + dr[rr + 2][p];
                float gy = vd[rr][p] + 2.0f * vd[rr][p + 1] + vd[rr][p + 2];
                float m  = gx * gx + gy * gy + EPS64;      // 64x-scaled
                if (c == 0) {
                    bm[rr][p] = m; bgx[rr][p] = gx; bgy[rr][p] = gy;
                } else if (m > bm[rr][p]) {  // strict >: first-occurrence argmax
                    bm[rr][p] = m; bgx[rr][p] = gx; bgy[rr][p] = gy;
                }
            }
        }
    }

    const size_t oang = (size_t)BATCH * HW;

    #pragma unroll
    for (int rr = 0; rr < 2; rr++) {
        float4 mag, ang;
        mag.x = fsqrt_approx(bm[rr][0]) * 0.125f;   // == sqrt(m)/8 bitwise
        mag.y = fsqrt_approx(bm[rr][1]) * 0.125f;
        mag.z = fsqrt_approx(bm[rr][2]) * 0.125f;
        mag.w = fsqrt_approx(bm[rr][3]) * 0.125f;

        float y0 = (bgy[rr][0] == 0.f) ? TINY8 : bgy[rr][0];
        float y1 = (bgy[rr][1] == 0.f) ? TINY8 : bgy[rr][1];
        float y2 = (bgy[rr][2] == 0.f) ? TINY8 : bgy[rr][2];
        float y3 = (bgy[rr][3] == 0.f) ? TINY8 : bgy[rr][3];
        ang.x = fminf(fmaxf(__fdividef(bgx[rr][0], y0), -10.f), 10.f);
        ang.y = fminf(fmaxf(__fdividef(bgx[rr][1], y1), -10.f), 10.f);
        ang.z = fminf(fmaxf(__fdividef(bgx[rr][2], y2), -10.f), 10.f);
        ang.w = fminf(fmaxf(__fdividef(bgx[rr][3], y3), -10.f), 10.f);

        const size_t o = (size_t)b * HW + (size_t)(by0 + 2 * wy + rr) * WW + (bx0 + lc);
        *(float4*)(out + o)        = mag;
        *(float4*)(out + oang + o) = ang;
    }
}

extern "C" void kernel_launch(void* const* d_in, const int* in_sizes, int n_in,
                              void* d_out, int out_size)
{
    const float* x = (const float*)d_in[0];
    float* out = (float*)d_out;

    dim3 block(256, 1, 1);
    dim3 grid(WW / TILE_W, HH / TILE_H, BATCH);   // (4, 32, 16) = 2048 blocks
    sobel_kernel<<<grid, block>>>(x, out);
}

// round 12
// speedup vs baseline: 1.6840x; 1.6840x over previous
#include <cuda_runtime.h>
#include <cuda_pipeline.h>

// Sobel_16724602651101 — R11
// x: (16, 3, 512, 512) fp32 -> out: [magnitude | angle] each (16,512,512) fp32.
//
// cp.async smem staging (RF-free MLP) with LEAN indexing:
//  - warp=row / lane=16B-group mapping, fully unrolled, no div/mod
//  - all blocks take the vector path; x-edge halo fixed by a 54-write patch
//  - conflict-free LDS (float2/float4/float2) in compute
// Numeric trees frozen from the R1-R10 lineage (R1 grouping, exact
// power-of-two deferred scaling, sqrt.approx + __fdividef; rel_err 1.0849e-7).

#define BATCH 16
#define CH 3
#define HH 512
#define WW 512
#define HW (HH * WW)

#define TILE_W 128
#define TILE_H 16
#define LH 18            // halo rows per channel
#define LPITCH 136       // halo cols: j <-> global col bx0-4+j ; used j = 3..132

#define EPS64 (64.0f * 1e-9f)
#define TINY8 (8.0f * 1e-9f)

__device__ __forceinline__ float fsqrt_approx(float a)
{
    float r;
    asm("sqrt.approx.f32 %0, %1;" : "=f"(r) : "f"(a));
    return r;
}

__global__ __launch_bounds__(256, 4)
void sobel_kernel(const float* __restrict__ x, float* __restrict__ out)
{
    __shared__ __align__(16) float s[CH][LH][LPITCH];

    const int bx0 = blockIdx.x * TILE_W;
    const int by0 = blockIdx.y * TILE_H;
    const int b   = blockIdx.z;
    const int tid = threadIdx.x;
    const int lane = tid & 31;
    const int wid  = tid >> 5;

    const float* __restrict__ xb = x + (size_t)b * CH * HW;

    // ---- load phase: warp=row, lane=16B group; no div/mod ----
    // main groups g=lane (j=4*lane, cols bx0-4+4*lane), clamped to [0,508]
    const int col_a = min(max(bx0 - 4 + 4 * lane, 0), WW - 4);
    // tail groups g=32+lane for lane<2 (j=128+4*lane)
    const int col_b = min(max(bx0 + 124 + 4 * lane, 0), WW - 4);

    #pragma unroll
    for (int c = 0; c < CH; c++) {
        const float* __restrict__ xc = xb + c * HW;
        #pragma unroll
        for (int k = 0; k < 3; k++) {
            const int r = wid + 8 * k;            // 0..23; valid r<18
            if (k < 2 || wid < 2) {
                const int gr = min(max(by0 - 1 + r, 0), HH - 1);
                const float* __restrict__ rp = xc + gr * WW;
                __pipeline_memcpy_async(&s[c][r][4 * lane], rp + col_a, 16);
                if (lane < 2)
                    __pipeline_memcpy_async(&s[c][r][128 + 4 * lane], rp + col_b, 16);
            }
        }
    }
    __pipeline_commit();
    __pipeline_wait_prior(0);
    __syncthreads();

    // ---- x-edge halo patch (block-uniform branch; 54 scalar smem writes) ----
    if (bx0 == 0) {
        if (tid < CH * LH) {
            int c = tid / LH, r = tid - c * LH;
            s[c][r][3] = s[c][r][4];              // col -1 := col 0
        }
        __syncthreads();
    } else if (bx0 + TILE_W == WW) {
        if (tid < CH * LH) {
            int c = tid / LH, r = tid - c * LH;
            s[c][r][132] = s[c][r][131];          // col 512 := col 511
        }
        __syncthreads();
    }

    // ---- compute: 4 cols x 2 rows per thread ----
    const int lc = 4 * lane;                      // window local cols lc+3..lc+8
    const int wy = wid;                           // out rows by0+2wy, +2wy+1

    float bm[2][4], bgx[2][4], bgy[2][4];

    #pragma unroll
    for (int c = 0; c < CH; c++) {
        // 4 input rows (local 2wy..2wy+3) x 6 cols, conflict-free LDS
        float w[4][6];
        #pragma unroll
        for (int i = 0; i < 4; i++) {
            const float* __restrict__ row = &s[c][2 * wy + i][0];
            float2 va = *(const float2*)(row + lc + 2);   // cols lc+2, lc+3
            float4 v  = *(const float4*)(row + lc + 4);   // cols lc+4..lc+7
            float2 vb = *(const float2*)(row + lc + 8);   // cols lc+8, lc+9
            w[i][0] = va.y;
            w[i][1] = v.x; w[i][2] = v.y; w[i][3] = v.z; w[i][4] = v.w;
            w[i][5] = vb.x;
        }

        // horizontal diffs once per input row (rows 1,2 shared by both outputs)
        float dr[4][4];
        #pragma unroll
        for (int i = 0; i < 4; i++)
            #pragma unroll
            for (int p = 0; p < 4; p++) dr[i][p] = w[i][p + 2] - w[i][p];

        // vertical diffs per output row
        float vd[2][6];
        #pragma unroll
        for (int j = 0; j < 6; j++) { vd[0][j] = w[2][j] - w[0][j];
                                      vd[1][j] = w[3][j] - w[1][j]; }

        #pragma unroll
        for (int rr = 0; rr < 2; rr++) {
            #pragma unroll
            for (int p = 0; p < 4; p++) {
                // 8x-scaled gx/gy, R1's exact grouping
                float gx = dr[rr][p] + 2.0f * dr[rr + 1][p] + dr[rr + 2][p];
                float gy = vd[rr][p] + 2.0f * vd[rr][p + 1] + vd[rr][p + 2];
                float m  = gx * gx + gy * gy + EPS64;      // 64x-scaled
                if (c == 0) {
                    bm[rr][p] = m; bgx[rr][p] = gx; bgy[rr][p] = gy;
                } else if (m > bm[rr][p]) {   // strict >: first-occurrence argmax
                    bm[rr][p] = m; bgx[rr][p] = gx; bgy[rr][p] = gy;
                }
            }
        }
    }

    const size_t oang = (size_t)BATCH * HW;

    #pragma unroll
    for (int rr = 0; rr < 2; rr++) {
        float4 mag, ang;
        mag.x = fsqrt_approx(bm[rr][0]) * 0.125f;   // == sqrt(m)/8 bitwise
        mag.y = fsqrt_approx(bm[rr][1]) * 0.125f;
        mag.z = fsqrt_approx(bm[rr][2]) * 0.125f;
        mag.w = fsqrt_approx(bm[rr][3]) * 0.125f;

        float y0 = (bgy[rr][0] == 0.f) ? TINY8 : bgy[rr][0];
        float y1 = (bgy[rr][1] == 0.f) ? TINY8 : bgy[rr][1];
        float y2 = (bgy[rr][2] == 0.f) ? TINY8 : bgy[rr][2];
        float y3 = (bgy[rr][3] == 0.f) ? TINY8 : bgy[rr][3];
        ang.x = fminf(fmaxf(__fdividef(bgx[rr][0], y0), -10.f), 10.f);
        ang.y = fminf(fmaxf(__fdividef(bgx[rr][1], y1), -10.f), 10.f);
        ang.z = fminf(fmaxf(__fdividef(bgx[rr][2], y2), -10.f), 10.f);
        ang.w = fminf(fmaxf(__fdividef(bgx[rr][3], y3), -10.f), 10.f);

        const size_t o = (size_t)b * HW + (size_t)(by0 + 2 * wy + rr) * WW + (bx0 + lc);
        *(float4*)(out + o)        = mag;
        *(float4*)(out + oang + o) = ang;
    }
}

extern "C" void kernel_launch(void* const* d_in, const int* in_sizes, int n_in,
                              void* d_out, int out_size)
{
    const float* x = (const float*)d_in[0];
    float* out = (float*)d_out;

    dim3 block(256, 1, 1);
    dim3 grid(WW / TILE_W, HH / TILE_H, BATCH);   // (4, 32, 16) = 2048 blocks
    sobel_kernel<<<grid, block>>>(x, out);
}